// round 15
// baseline (speedup 1.0000x reference)
#include <cuda_runtime.h>
#include <cuda_bf16.h>
#include <math.h>
#include <stdint.h>

#define QD 256    // queries
#define II 2048   // gallery images
#define DD 256    // feature dim

#define TM 64     // i per CTA
#define TN 32     // q per CTA

// smem rows: 256 bf16 = 512 B + 16 pad = 528 B; 528 ≡ 4*4B banks (mod 32):
// each 8-row ldmatrix phase covers all 32 banks exactly once -> conflict-free.
#define SKB 528
#define OFF_G  0
#define OFF_C  (OFF_G + TM * SKB)       // 33792
#define OFF_A2 (OFF_C + TN * SKB)       // 50688
#define OFF_AB (OFF_A2 + TN * SKB)      // 67584
#define SMEM_SZ (OFF_AB + TN * SKB)     // 84480 B -> 2 CTAs/SM

// ---- bf16 operand arrays (natural [row][k] layouts) ----
__device__ __align__(16) __nv_bfloat16 d_Gb [II * DD];  // normalized gallery
__device__ __align__(16) __nv_bfloat16 d_Cb [QD * DD];  // fqn*A
__device__ __align__(16) __nv_bfloat16 d_A2b[QD * DD];  // A^2
__device__ __align__(16) __nv_bfloat16 d_ABb[QD * DD];  // 2*A*B
__device__ float d_c0[QD];
__device__ float d_b0;

// ---------------- PTX helpers ----------------
#define CP16(dst_u32, src_ptr) \
    asm volatile("cp.async.cg.shared.global [%0], [%1], 16;" \
                 :: "r"(dst_u32), "l"(src_ptr) : "memory")
#define CPCOMMIT() asm volatile("cp.async.commit_group;" ::: "memory")
#define CPWAIT0()  asm volatile("cp.async.wait_group 0;" ::: "memory")

#define LDSM_X4(r0, r1, r2, r3, addr) \
    asm volatile("ldmatrix.sync.aligned.m8n8.x4.shared.b16 {%0,%1,%2,%3}, [%4];" \
                 : "=r"(r0), "=r"(r1), "=r"(r2), "=r"(r3) : "r"(addr))

#define MMA16816(d, a, b0v, b1v) \
    asm volatile("mma.sync.aligned.m16n8k16.row.col.f32.bf16.bf16.f32 " \
                 "{%0,%1,%2,%3}, {%4,%5,%6,%7}, {%8,%9}, {%0,%1,%2,%3};" \
                 : "+f"((d)[0]), "+f"((d)[1]), "+f"((d)[2]), "+f"((d)[3]) \
                 : "r"((a)[0]), "r"((a)[1]), "r"((a)[2]), "r"((a)[3]), \
                   "r"(b0v), "r"(b1v))

#define SQR_BF16X2(d, a) \
    asm("mul.bf16x2 %0, %1, %1;" : "=r"(d) : "r"(a))

// pack two fp32 -> one bf16x2 register (no union, no local memory)
#define CVT2(dst, lo, hi) \
    asm("cvt.rn.bf16x2.f32 %0, %1, %2;" : "=r"(dst) : "f"(hi), "f"(lo))

__device__ __forceinline__ float warpSum(float v) {
    #pragma unroll
    for (int o = 16; o; o >>= 1) v += __shfl_xor_sync(0xffffffffu, v, o);
    return v;
}

__device__ __forceinline__ uint4 pack8(const float* f) {
    uint4 u;
    CVT2(u.x, f[0], f[1]);
    CVT2(u.y, f[2], f[3]);
    CVT2(u.z, f[4], f[5]);
    CVT2(u.w, f[6], f[7]);
    return u;
}

// ---------------- prep kernel: 288 blocks x 256 threads ----------------
// blocks 0..255 : gallery rows (warp per row); 256..287 : queries (warp per q)
__global__ __launch_bounds__(256) void prep_kernel(
        const float* __restrict__ qf,
        const float* __restrict__ qi,
        const float* __restrict__ gal,
        const float* __restrict__ gamma,
        const float* __restrict__ beta,
        const float* __restrict__ mean,
        const float* __restrict__ var) {
    const int bx   = blockIdx.x;
    const int warp = threadIdx.x >> 5;
    const int lane = threadIdx.x & 31;

    if (bx < 256) {
        const int i = bx * 8 + warp;
        float x[8];
        {
            const float4* s4 = (const float4*)&gal[(size_t)i * DD + lane * 8];
            *(float4*)&x[0] = s4[0];
            *(float4*)&x[4] = s4[1];
        }
        float ss = 0.f;
        #pragma unroll
        for (int j = 0; j < 8; j++) ss += x[j] * x[j];
        ss = warpSum(ss);
        float inv = 1.f / fmaxf(sqrtf(ss), 1e-12f);
        float g[8];
        #pragma unroll
        for (int j = 0; j < 8; j++) g[j] = x[j] * inv;
        *(uint4*)&d_Gb[(size_t)i * DD + lane * 8] = pack8(g);
    } else {
        const int q = (bx - 256) * 8 + warp;

        float ga[8], be[8], me[8], va[8], x[8], y[8];
        {
            const float4* s;
            s = (const float4*)&gamma[lane * 8]; *(float4*)&ga[0] = s[0]; *(float4*)&ga[4] = s[1];
            s = (const float4*)&beta [lane * 8]; *(float4*)&be[0] = s[0]; *(float4*)&be[4] = s[1];
            s = (const float4*)&mean [lane * 8]; *(float4*)&me[0] = s[0]; *(float4*)&me[4] = s[1];
            s = (const float4*)&var  [lane * 8]; *(float4*)&va[0] = s[0]; *(float4*)&va[4] = s[1];
            s = (const float4*)&qf[(size_t)q * DD + lane * 8]; *(float4*)&x[0] = s[0]; *(float4*)&x[4] = s[1];
            s = (const float4*)&qi[(size_t)q * DD + lane * 8]; *(float4*)&y[0] = s[0]; *(float4*)&y[4] = s[1];
        }

        float istd[8], B[8];
        float xs = 0.f, ys = 0.f;
        #pragma unroll
        for (int j = 0; j < 8; j++) {
            istd[j] = ga[j] * rsqrtf(va[j] + 1e-5f);
            B[j] = be[j] - me[j] * istd[j];
            xs += x[j] * x[j];
            ys += y[j] * y[j];
        }
        xs = warpSum(xs);
        ys = warpSum(ys);
        float xin = 1.f / fmaxf(sqrtf(xs), 1e-12f);
        float yin = 1.f / fmaxf(sqrtf(ys), 1e-12f);

        float A[8], fq[8];
        float fs = 0.f;
        #pragma unroll
        for (int j = 0; j < 8; j++) {
            float xn = x[j] * xin;
            float gate = 1.f / (1.f + __expf(-xn * 5.0f));  // sigmoid(xn/0.2)
            A[j] = gate * istd[j];
            float yn = y[j] * yin;
            fq[j] = yn * A[j] + B[j];
            fs += fq[j] * fq[j];
        }
        fs = warpSum(fs);
        float fin = 1.f / fmaxf(sqrtf(fs), 1e-12f);

        float Cv[8], A2v[8], ABv[8];
        float c0 = 0.f;
        #pragma unroll
        for (int j = 0; j < 8; j++) {
            float fqn = fq[j] * fin;
            Cv[j]  = fqn * A[j];
            A2v[j] = A[j] * A[j];
            ABv[j] = 2.f * A[j] * B[j];
            c0 += fqn * B[j];
        }
        c0 = warpSum(c0);
        if (lane == 0) d_c0[q] = c0;

        *(uint4*)&d_Cb [(size_t)q * DD + lane * 8] = pack8(Cv);
        *(uint4*)&d_A2b[(size_t)q * DD + lane * 8] = pack8(A2v);
        *(uint4*)&d_ABb[(size_t)q * DD + lane * 8] = pack8(ABv);

        if (q == 0) {
            float b0 = 0.f;
            #pragma unroll
            for (int j = 0; j < 8; j++) b0 += B[j] * B[j];
            b0 = warpSum(b0);
            if (lane == 0) d_b0 = b0;
        }
    }
}

// ---------------- HMMA scoring kernel ----------------
// grid (II/TM, QD/TN) = (32, 8) = 256 CTAs; 512 threads = 16 warps (4 i x 4 q).
// 2 CTAs co-resident per SM (84.5 KB smem each) -> load/compute phase overlap.
// Warp tile 16i x 8q: single m16n8 accumulator per matrix.
// Single-shot cp.async of the full K=256 working set, one wait + one sync,
// then a straight barrier-free HMMA sweep; G2 via register bf16x2 squaring.
extern __shared__ __align__(16) char dyn_smem[];

__global__ __launch_bounds__(512, 2) void score_kernel(float* __restrict__ out) {
    const int tid  = threadIdx.x;
    const int warp = tid >> 5;
    const int lane = tid & 31;
    const int wm = warp & 3;       // i block (16 rows)
    const int wn = warp >> 2;      // q block (8 cols)
    const int i0 = blockIdx.x * TM;
    const int q0 = blockIdx.y * TN;

    const uint32_t sb = (uint32_t)__cvta_generic_to_shared(dyn_smem);

    // ---- single-shot async load of the full working set ----
    // G: 64 rows x 32 16B-units = 2048 units -> 4 per thread
    #pragma unroll
    for (int j = 0; j < 4; j++) {
        int u = tid + 512 * j;
        int row = u >> 5;             // 0..63
        int c16 = u & 31;             // 16B unit in 512B row
        const size_t src = (size_t)(i0 + row) * DD + c16 * 8;
        CP16(sb + OFF_G + row * SKB + c16 * 16, &d_Gb[src]);
    }
    // coeffs: 3 arrays x 32 rows x 32 units = 1024 units each -> 2 per thread
    #pragma unroll
    for (int j = 0; j < 2; j++) {
        int u = tid + 512 * j;
        int row = u >> 5;             // 0..31
        int c16 = u & 31;
        const size_t src = (size_t)(q0 + row) * DD + c16 * 8;
        uint32_t dst = row * SKB + c16 * 16;
        CP16(sb + OFF_C  + dst, &d_Cb [src]);
        CP16(sb + OFF_A2 + dst, &d_A2b[src]);
        CP16(sb + OFF_AB + dst, &d_ABb[src]);
    }
    CPCOMMIT();
    CPWAIT0();
    __syncthreads();

    // ---- straight HMMA over K = 256, no barriers ----
    float s1[4], s2[4];
    #pragma unroll
    for (int r = 0; r < 4; r++) { s1[r] = 0.f; s2[r] = 0.f; }

    const int subA = lane >> 3;
    const int arow = (lane & 7) + (subA & 1) * 8;
    const int akof = (subA >> 1) * 16;
    const int brow = lane & 7;
    const int bkof = (lane >> 3) * 16;

    const uint32_t gA  = sb + OFF_G  + (wm * 16 + arow) * SKB + akof;
    const uint32_t cB  = sb + OFF_C  + (wn * 8 + brow) * SKB + bkof;
    const uint32_t a2B = sb + OFF_A2 + (wn * 8 + brow) * SKB + bkof;
    const uint32_t abB = sb + OFF_AB + (wn * 8 + brow) * SKB + bkof;

    #pragma unroll
    for (int p = 0; p < 8; p++) {              // 8 pairs of k16 (k32 each)
        const uint32_t pb = p * 64;            // 32 bf16 = 64 B

        uint32_t bC[4], bA2[4], bAB[4];
        LDSM_X4(bC[0],  bC[1],  bC[2],  bC[3],  cB  + pb);
        LDSM_X4(bA2[0], bA2[1], bA2[2], bA2[3], a2B + pb);
        LDSM_X4(bAB[0], bAB[1], bAB[2], bAB[3], abB + pb);

        #pragma unroll
        for (int e = 0; e < 2; e++) {
            const uint32_t kb = pb + e * 32;
            uint32_t aG[4], aG2[4];
            LDSM_X4(aG[0], aG[1], aG[2], aG[3], gA + kb);
            #pragma unroll
            for (int r = 0; r < 4; r++) SQR_BF16X2(aG2[r], aG[r]);

            MMA16816(s1, aG,  bC[2*e],  bC[2*e+1]);
            MMA16816(s2, aG2, bA2[2*e], bA2[2*e+1]);
            MMA16816(s2, aG,  bAB[2*e], bAB[2*e+1]);
        }
    }

    // ---- epilogue ----
    const float b0 = d_b0;
    const int rbase = lane >> 2;
    const int cbase = 2 * (lane & 3);
    const float c0a = d_c0[q0 + wn * 8 + cbase];
    const float c0b = d_c0[q0 + wn * 8 + cbase + 1];
    #pragma unroll
    for (int r = 0; r < 4; r++) {
        int i = i0 + wm * 16 + rbase + (r >> 1) * 8;
        int q = q0 + wn * 8 + cbase + (r & 1);
        float v1 = s1[r] + ((r & 1) ? c0b : c0a);
        float v2 = s2[r] + b0;
        float val = v1 * rsqrtf(fmaxf(v2, 1e-24f));
        out[(size_t)q * II + i] = 1.f / (1.f + __expf(-val));
    }
}

extern "C" void kernel_launch(void* const* d_in, const int* in_sizes, int n_in,
                              void* d_out, int out_size) {
    const float* query_feats       = (const float*)d_in[0];
    const float* query_img_feats   = (const float*)d_in[1];
    const float* gallery_img_feats = (const float*)d_in[2];
    const float* bn_gamma          = (const float*)d_in[3];
    const float* bn_beta           = (const float*)d_in[4];
    const float* bn_mean           = (const float*)d_in[5];
    const float* bn_var            = (const float*)d_in[6];
    float* out = (float*)d_out;

    cudaFuncSetAttribute(score_kernel,
                         cudaFuncAttributeMaxDynamicSharedMemorySize, SMEM_SZ);

    prep_kernel<<<288, 256>>>(query_feats, query_img_feats, gallery_img_feats,
                              bn_gamma, bn_beta, bn_mean, bn_var);
    dim3 grid(II / TM, QD / TN);
    score_kernel<<<grid, 512, SMEM_SZ>>>(out);
}

// round 16
// speedup vs baseline: 1.0173x; 1.0173x over previous
#include <cuda_runtime.h>
#include <cuda_bf16.h>
#include <math.h>
#include <stdint.h>

#define QD 256    // queries
#define II 2048   // gallery images
#define DD 256    // feature dim

#define TM 128    // i per CTA
#define TN 32     // q per CTA

// smem rows: 256 bf16 = 512 B + 16 pad = 528 B; 528 ≡ 4 banks (mod 32):
// each 8-row ldmatrix phase covers all 32 banks exactly once -> conflict-free.
#define SKB 528
#define OFF_G  0
#define OFF_C  (OFF_G + TM * SKB)       // 67584
#define OFF_A2 (OFF_C + TN * SKB)       // 84480
#define OFF_AB (OFF_A2 + TN * SKB)      // 101376
#define SMEM_SZ (OFF_AB + TN * SKB)     // 118272 B (opt-in)

// output staging (reuses OFF_G region after mainloop): 32 q x pitch 132 fp32
#define OPITCH 132

// ---------------- PTX helpers ----------------
#define LDSM_X4(r0, r1, r2, r3, addr) \
    asm volatile("ldmatrix.sync.aligned.m8n8.x4.shared.b16 {%0,%1,%2,%3}, [%4];" \
                 : "=r"(r0), "=r"(r1), "=r"(r2), "=r"(r3) : "r"(addr))

#define MMA16816(d, a, b0v, b1v) \
    asm volatile("mma.sync.aligned.m16n8k16.row.col.f32.bf16.bf16.f32 " \
                 "{%0,%1,%2,%3}, {%4,%5,%6,%7}, {%8,%9}, {%0,%1,%2,%3};" \
                 : "+f"((d)[0]), "+f"((d)[1]), "+f"((d)[2]), "+f"((d)[3]) \
                 : "r"((a)[0]), "r"((a)[1]), "r"((a)[2]), "r"((a)[3]), \
                   "r"(b0v), "r"(b1v))

#define SQR_BF16X2(d, a) \
    asm("mul.bf16x2 %0, %1, %1;" : "=r"(d) : "r"(a))

// pack two fp32 -> one bf16x2 register (no union, no local memory)
#define CVT2(dst, lo, hi) \
    asm("cvt.rn.bf16x2.f32 %0, %1, %2;" : "=r"(dst) : "f"(hi), "f"(lo))

__device__ __forceinline__ float warpSum(float v) {
    #pragma unroll
    for (int o = 16; o; o >>= 1) v += __shfl_xor_sync(0xffffffffu, v, o);
    return v;
}

__device__ __forceinline__ uint4 pack8(const float* f) {
    uint4 u;
    CVT2(u.x, f[0], f[1]);
    CVT2(u.y, f[2], f[3]);
    CVT2(u.z, f[4], f[5]);
    CVT2(u.w, f[6], f[7]);
    return u;
}

// ---------------- fused scoring kernel ----------------
// grid (II/TM, QD/TN) = (16, 8) = 128 CTAs; 512 threads = 16 warps (4 i x 4 q).
// Phase 1 (fill): normalize gallery rows (8/warp) + query chain (2 q/warp),
//   bf16 tiles to smem via cvt.rn.bf16x2 (no local-memory pack).
// Phase 2: barrier-free HMMA sweep over K=256; G2 fragments by register
//   bf16x2 squaring. s1 = C.G^T ; s2 = A2.G2^T + AB.G^T.
// Phase 3: sigmoid((s1+c0)/sqrt(s2+b0)) -> smem staging -> coalesced STG.128.
extern __shared__ __align__(16) char dyn_smem[];

__global__ __launch_bounds__(512) void score_kernel(
        float* __restrict__ out,
        const float* __restrict__ qf,
        const float* __restrict__ qi,
        const float* __restrict__ gal,
        const float* __restrict__ gamma,
        const float* __restrict__ beta,
        const float* __restrict__ mean,
        const float* __restrict__ var) {
    const int tid  = threadIdx.x;
    const int warp = tid >> 5;
    const int lane = tid & 31;
    const int wm = warp & 3;       // i block (32 rows)
    const int wn = warp >> 2;      // q block (8 cols)
    const int i0 = blockIdx.x * TM;
    const int q0 = blockIdx.y * TN;

    const uint32_t sb = (uint32_t)__cvta_generic_to_shared(dyn_smem);
    __shared__ float sc0[TN];
    __shared__ float sb0;

    // ---- phase 1a: gallery rows (warp handles 8 rows; lane owns 8 d's) ----
    #pragma unroll
    for (int r = 0; r < 8; r++) {
        int row = warp * 8 + r;
        float x[8];
        {
            const float4* s4 = (const float4*)&gal[(size_t)(i0 + row) * DD + lane * 8];
            *(float4*)&x[0] = s4[0];
            *(float4*)&x[4] = s4[1];
        }
        float ss = 0.f;
        #pragma unroll
        for (int j = 0; j < 8; j++) ss += x[j] * x[j];
        ss = warpSum(ss);
        float inv = 1.f / fmaxf(sqrtf(ss), 1e-12f);
        float g[8];
        #pragma unroll
        for (int j = 0; j < 8; j++) g[j] = x[j] * inv;
        *(uint4*)(dyn_smem + OFF_G + row * SKB + lane * 16) = pack8(g);
    }

    // ---- phase 1b: query chain (warp handles 2 q rows) ----
    {
        float ga[8], be[8], me[8], va[8];
        {
            const float4* s;
            s = (const float4*)&gamma[lane * 8]; *(float4*)&ga[0] = s[0]; *(float4*)&ga[4] = s[1];
            s = (const float4*)&beta [lane * 8]; *(float4*)&be[0] = s[0]; *(float4*)&be[4] = s[1];
            s = (const float4*)&mean [lane * 8]; *(float4*)&me[0] = s[0]; *(float4*)&me[4] = s[1];
            s = (const float4*)&var  [lane * 8]; *(float4*)&va[0] = s[0]; *(float4*)&va[4] = s[1];
        }
        float istd[8], B[8];
        #pragma unroll
        for (int j = 0; j < 8; j++) {
            istd[j] = ga[j] * rsqrtf(va[j] + 1e-5f);
            B[j] = be[j] - me[j] * istd[j];
        }

        #pragma unroll
        for (int r = 0; r < 2; r++) {
            int ql = warp * 2 + r;
            int q  = q0 + ql;
            float x[8], y[8];
            {
                const float4* s;
                s = (const float4*)&qf[(size_t)q * DD + lane * 8]; *(float4*)&x[0] = s[0]; *(float4*)&x[4] = s[1];
                s = (const float4*)&qi[(size_t)q * DD + lane * 8]; *(float4*)&y[0] = s[0]; *(float4*)&y[4] = s[1];
            }
            float xs = 0.f, ys = 0.f;
            #pragma unroll
            for (int j = 0; j < 8; j++) { xs += x[j] * x[j]; ys += y[j] * y[j]; }
            xs = warpSum(xs);
            ys = warpSum(ys);
            float xin = 1.f / fmaxf(sqrtf(xs), 1e-12f);
            float yin = 1.f / fmaxf(sqrtf(ys), 1e-12f);

            float A[8], fq[8];
            float fs = 0.f;
            #pragma unroll
            for (int j = 0; j < 8; j++) {
                float xn = x[j] * xin;
                float gate = 1.f / (1.f + __expf(-xn * 5.0f));  // sigmoid(xn/0.2)
                A[j] = gate * istd[j];
                float yn = y[j] * yin;
                fq[j] = yn * A[j] + B[j];
                fs += fq[j] * fq[j];
            }
            fs = warpSum(fs);
            float fin = 1.f / fmaxf(sqrtf(fs), 1e-12f);

            float Cv[8], A2v[8], ABv[8];
            float c0 = 0.f;
            #pragma unroll
            for (int j = 0; j < 8; j++) {
                float fqn = fq[j] * fin;
                Cv[j]  = fqn * A[j];
                A2v[j] = A[j] * A[j];
                ABv[j] = 2.f * A[j] * B[j];
                c0 += fqn * B[j];
            }
            c0 = warpSum(c0);
            if (lane == 0) sc0[ql] = c0;

            *(uint4*)(dyn_smem + OFF_C  + ql * SKB + lane * 16) = pack8(Cv);
            *(uint4*)(dyn_smem + OFF_A2 + ql * SKB + lane * 16) = pack8(A2v);
            *(uint4*)(dyn_smem + OFF_AB + ql * SKB + lane * 16) = pack8(ABv);

            if (warp == 0 && r == 0) {
                float b0 = 0.f;
                #pragma unroll
                for (int j = 0; j < 8; j++) b0 += B[j] * B[j];
                b0 = warpSum(b0);
                if (lane == 0) sb0 = b0;
            }
        }
    }

    __syncthreads();

    // ---- phase 2: straight HMMA over K = 256, no barriers ----
    float s1[2][4], s2[2][4];
    #pragma unroll
    for (int ma = 0; ma < 2; ma++)
        #pragma unroll
        for (int r = 0; r < 4; r++) { s1[ma][r] = 0.f; s2[ma][r] = 0.f; }

    const int subA = lane >> 3;
    const int arow = (lane & 7) + (subA & 1) * 8;
    const int akof = (subA >> 1) * 16;
    const int brow = lane & 7;
    const int bkof = (lane >> 3) * 16;

    const uint32_t gA0 = sb + OFF_G  + (wm * 32 + arow) * SKB + akof;
    const uint32_t gA1 = gA0 + 16 * SKB;
    const uint32_t cB  = sb + OFF_C  + (wn * 8 + brow) * SKB + bkof;
    const uint32_t a2B = sb + OFF_A2 + (wn * 8 + brow) * SKB + bkof;
    const uint32_t abB = sb + OFF_AB + (wn * 8 + brow) * SKB + bkof;

    #pragma unroll
    for (int p = 0; p < 8; p++) {              // 8 pairs of k16 (k32 each)
        const uint32_t pb = p * 64;

        uint32_t bC[4], bA2[4], bAB[4];
        LDSM_X4(bC[0],  bC[1],  bC[2],  bC[3],  cB  + pb);
        LDSM_X4(bA2[0], bA2[1], bA2[2], bA2[3], a2B + pb);
        LDSM_X4(bAB[0], bAB[1], bAB[2], bAB[3], abB + pb);

        #pragma unroll
        for (int e = 0; e < 2; e++) {
            const uint32_t kb = pb + e * 32;
            uint32_t aG[2][4], aG2[2][4];
            LDSM_X4(aG[0][0], aG[0][1], aG[0][2], aG[0][3], gA0 + kb);
            LDSM_X4(aG[1][0], aG[1][1], aG[1][2], aG[1][3], gA1 + kb);
            #pragma unroll
            for (int ma = 0; ma < 2; ma++)
                #pragma unroll
                for (int r = 0; r < 4; r++)
                    SQR_BF16X2(aG2[ma][r], aG[ma][r]);

            #pragma unroll
            for (int ma = 0; ma < 2; ma++) {
                MMA16816(s1[ma], aG[ma],  bC[2*e],  bC[2*e+1]);
                MMA16816(s2[ma], aG2[ma], bA2[2*e], bA2[2*e+1]);
                MMA16816(s2[ma], aG[ma],  bAB[2*e], bAB[2*e+1]);
            }
        }
    }

    // ---- phase 3: sigmoid, smem staging, coalesced store ----
    __syncthreads();   // all warps done reading tiles; OFF_G region reusable

    float* sOut = (float*)dyn_smem;   // [32 q][pitch 132] fp32 = 16.9 KB
    const float b0 = sb0;
    const int rbase = lane >> 2;
    const int cbase = 2 * (lane & 3);
    const float c0a = sc0[wn * 8 + cbase];
    const float c0b = sc0[wn * 8 + cbase + 1];
    #pragma unroll
    for (int ma = 0; ma < 2; ma++) {
        #pragma unroll
        for (int r = 0; r < 4; r++) {
            int il = wm * 32 + ma * 16 + rbase + (r >> 1) * 8;
            int ql = wn * 8 + cbase + (r & 1);
            float v1 = s1[ma][r] + ((r & 1) ? c0b : c0a);
            float v2 = s2[ma][r] + b0;
            float val = v1 * rsqrtf(fmaxf(v2, 1e-24f));
            sOut[ql * OPITCH + il] = 1.f / (1.f + __expf(-val));
        }
    }
    __syncthreads();

    // warp handles q rows 2*warp, 2*warp+1: lane stores float4 (coalesced)
    #pragma unroll
    for (int r = 0; r < 2; r++) {
        int ql = warp * 2 + r;
        float4 v = *(const float4*)&sOut[ql * OPITCH + lane * 4];
        *(float4*)&out[(size_t)(q0 + ql) * II + i0 + lane * 4] = v;
    }
}

extern "C" void kernel_launch(void* const* d_in, const int* in_sizes, int n_in,
                              void* d_out, int out_size) {
    const float* query_feats       = (const float*)d_in[0];
    const float* query_img_feats   = (const float*)d_in[1];
    const float* gallery_img_feats = (const float*)d_in[2];
    const float* bn_gamma          = (const float*)d_in[3];
    const float* bn_beta           = (const float*)d_in[4];
    const float* bn_mean           = (const float*)d_in[5];
    const float* bn_var            = (const float*)d_in[6];
    float* out = (float*)d_out;

    cudaFuncSetAttribute(score_kernel,
                         cudaFuncAttributeMaxDynamicSharedMemorySize, SMEM_SZ);

    dim3 grid(II / TM, QD / TN);
    score_kernel<<<grid, 512, SMEM_SZ>>>(out, query_feats, query_img_feats,
                                         gallery_img_feats, bn_gamma, bn_beta,
                                         bn_mean, bn_var);
}

// round 17
// speedup vs baseline: 1.1544x; 1.1348x over previous
#include <cuda_runtime.h>
#include <cuda_bf16.h>
#include <math.h>
#include <stdint.h>

#define QD 256    // queries
#define II 2048   // gallery images
#define DD 256    // feature dim

#define TM 128    // i per CTA
#define TN 32     // q per CTA

// smem rows: 256 bf16 = 512 B + 16 pad = 528 B; 528 ≡ 4 banks (mod 32):
// each 8-row ldmatrix phase covers all 32 banks exactly once -> conflict-free.
#define SKB 528
#define OFF_G  0
#define OFF_C  (OFF_G + TM * SKB)       // 67584
#define OFF_A2 (OFF_C + TN * SKB)       // 84480
#define OFF_AB (OFF_A2 + TN * SKB)      // 101376
#define SMEM_SZ (OFF_AB + TN * SKB)     // 118272 B (opt-in)

#define OPITCH 132   // fp32 output staging pitch (conflict-free, 16B-aligned)

// ---- bf16 operand arrays (natural [row][k] layouts) ----
__device__ __align__(16) __nv_bfloat16 d_Gb [II * DD];  // normalized gallery
__device__ __align__(16) __nv_bfloat16 d_Cb [QD * DD];  // fqn*A
__device__ __align__(16) __nv_bfloat16 d_A2b[QD * DD];  // A^2
__device__ __align__(16) __nv_bfloat16 d_ABb[QD * DD];  // 2*A*B
__device__ float d_c0[QD];
__device__ float d_b0;

// ---------------- PTX helpers ----------------
#define CP16(dst_u32, src_ptr) \
    asm volatile("cp.async.cg.shared.global [%0], [%1], 16;" \
                 :: "r"(dst_u32), "l"(src_ptr) : "memory")
#define CPCOMMIT() asm volatile("cp.async.commit_group;" ::: "memory")
#define CPWAIT1()  asm volatile("cp.async.wait_group 1;" ::: "memory")
#define CPWAIT0()  asm volatile("cp.async.wait_group 0;" ::: "memory")

#define LDSM_X4(r0, r1, r2, r3, addr) \
    asm volatile("ldmatrix.sync.aligned.m8n8.x4.shared.b16 {%0,%1,%2,%3}, [%4];" \
                 : "=r"(r0), "=r"(r1), "=r"(r2), "=r"(r3) : "r"(addr))

#define MMA16816(d, a, b0v, b1v) \
    asm volatile("mma.sync.aligned.m16n8k16.row.col.f32.bf16.bf16.f32 " \
                 "{%0,%1,%2,%3}, {%4,%5,%6,%7}, {%8,%9}, {%0,%1,%2,%3};" \
                 : "+f"((d)[0]), "+f"((d)[1]), "+f"((d)[2]), "+f"((d)[3]) \
                 : "r"((a)[0]), "r"((a)[1]), "r"((a)[2]), "r"((a)[3]), \
                   "r"(b0v), "r"(b1v))

#define SQR_BF16X2(d, a) \
    asm("mul.bf16x2 %0, %1, %1;" : "=r"(d) : "r"(a))

#define CVT2(dst, lo, hi) \
    asm("cvt.rn.bf16x2.f32 %0, %1, %2;" : "=r"(dst) : "f"(hi), "f"(lo))

__device__ __forceinline__ float warpSum(float v) {
    #pragma unroll
    for (int o = 16; o; o >>= 1) v += __shfl_xor_sync(0xffffffffu, v, o);
    return v;
}

__device__ __forceinline__ uint4 pack8(const float* f) {
    uint4 u;
    CVT2(u.x, f[0], f[1]);
    CVT2(u.y, f[2], f[3]);
    CVT2(u.z, f[4], f[5]);
    CVT2(u.w, f[6], f[7]);
    return u;
}

// ---------------- prep kernel: 288 blocks x 256 threads ----------------
// blocks 0..255 : gallery rows (warp per row); 256..287 : queries (warp per q)
__global__ __launch_bounds__(256) void prep_kernel(
        const float* __restrict__ qf,
        const float* __restrict__ qi,
        const float* __restrict__ gal,
        const float* __restrict__ gamma,
        const float* __restrict__ beta,
        const float* __restrict__ mean,
        const float* __restrict__ var) {
    const int bx   = blockIdx.x;
    const int warp = threadIdx.x >> 5;
    const int lane = threadIdx.x & 31;

    if (bx < 256) {
        const int i = bx * 8 + warp;
        float x[8];
        {
            const float4* s4 = (const float4*)&gal[(size_t)i * DD + lane * 8];
            *(float4*)&x[0] = s4[0];
            *(float4*)&x[4] = s4[1];
        }
        float ss = 0.f;
        #pragma unroll
        for (int j = 0; j < 8; j++) ss += x[j] * x[j];
        ss = warpSum(ss);
        float inv = 1.f / fmaxf(sqrtf(ss), 1e-12f);
        float g[8];
        #pragma unroll
        for (int j = 0; j < 8; j++) g[j] = x[j] * inv;
        *(uint4*)&d_Gb[(size_t)i * DD + lane * 8] = pack8(g);
    } else {
        const int q = (bx - 256) * 8 + warp;

        float ga[8], be[8], me[8], va[8], x[8], y[8];
        {
            const float4* s;
            s = (const float4*)&gamma[lane * 8]; *(float4*)&ga[0] = s[0]; *(float4*)&ga[4] = s[1];
            s = (const float4*)&beta [lane * 8]; *(float4*)&be[0] = s[0]; *(float4*)&be[4] = s[1];
            s = (const float4*)&mean [lane * 8]; *(float4*)&me[0] = s[0]; *(float4*)&me[4] = s[1];
            s = (const float4*)&var  [lane * 8]; *(float4*)&va[0] = s[0]; *(float4*)&va[4] = s[1];
            s = (const float4*)&qf[(size_t)q * DD + lane * 8]; *(float4*)&x[0] = s[0]; *(float4*)&x[4] = s[1];
            s = (const float4*)&qi[(size_t)q * DD + lane * 8]; *(float4*)&y[0] = s[0]; *(float4*)&y[4] = s[1];
        }

        float istd[8], B[8];
        float xs = 0.f, ys = 0.f;
        #pragma unroll
        for (int j = 0; j < 8; j++) {
            istd[j] = ga[j] * rsqrtf(va[j] + 1e-5f);
            B[j] = be[j] - me[j] * istd[j];
            xs += x[j] * x[j];
            ys += y[j] * y[j];
        }
        xs = warpSum(xs);
        ys = warpSum(ys);
        float xin = 1.f / fmaxf(sqrtf(xs), 1e-12f);
        float yin = 1.f / fmaxf(sqrtf(ys), 1e-12f);

        float A[8], fq[8];
        float fs = 0.f;
        #pragma unroll
        for (int j = 0; j < 8; j++) {
            float xn = x[j] * xin;
            float gate = 1.f / (1.f + __expf(-xn * 5.0f));  // sigmoid(xn/0.2)
            A[j] = gate * istd[j];
            float yn = y[j] * yin;
            fq[j] = yn * A[j] + B[j];
            fs += fq[j] * fq[j];
        }
        fs = warpSum(fs);
        float fin = 1.f / fmaxf(sqrtf(fs), 1e-12f);

        float Cv[8], A2v[8], ABv[8];
        float c0 = 0.f;
        #pragma unroll
        for (int j = 0; j < 8; j++) {
            float fqn = fq[j] * fin;
            Cv[j]  = fqn * A[j];
            A2v[j] = A[j] * A[j];
            ABv[j] = 2.f * A[j] * B[j];
            c0 += fqn * B[j];
        }
        c0 = warpSum(c0);
        if (lane == 0) d_c0[q] = c0;

        *(uint4*)&d_Cb [(size_t)q * DD + lane * 8] = pack8(Cv);
        *(uint4*)&d_A2b[(size_t)q * DD + lane * 8] = pack8(A2v);
        *(uint4*)&d_ABb[(size_t)q * DD + lane * 8] = pack8(ABv);

        if (q == 0) {
            float b0 = 0.f;
            #pragma unroll
            for (int j = 0; j < 8; j++) b0 += B[j] * B[j];
            b0 = warpSum(b0);
            if (lane == 0) d_b0 = b0;
        }
    }
}

// ---------------- HMMA scoring kernel ----------------
// grid (II/TM, QD/TN) = (16, 8) = 128 CTAs; 512 threads = 16 warps (4 i x 4 q).
// 2-phase pipelined load: K-half [0,128) committed first, compute on it while
// K-half [128,256) streams in. Barrier-free HMMA within each half; G2 via
// register bf16x2 squaring. Staged coalesced output via retired G region.
extern __shared__ __align__(16) char dyn_smem[];

__global__ __launch_bounds__(512) void score_kernel(float* __restrict__ out) {
    const int tid  = threadIdx.x;
    const int warp = tid >> 5;
    const int lane = tid & 31;
    const int wm = warp & 3;       // i block (32 rows)
    const int wn = warp >> 2;      // q block (8 cols)
    const int i0 = blockIdx.x * TM;
    const int q0 = blockIdx.y * TN;

    const uint32_t sb = (uint32_t)__cvta_generic_to_shared(dyn_smem);

    // ---- pipelined async load: two K-halves as separate commit groups ----
    #pragma unroll
    for (int h = 0; h < 2; h++) {
        const int kofB = h * 256;   // byte offset within row (128 k = 256 B)
        const int kofE = h * 128;   // element offset
        // G: 128 rows x 16 units per half -> 4 per thread
        #pragma unroll
        for (int j = 0; j < 4; j++) {
            int u = tid + 512 * j;
            int row = u >> 4;             // 0..127
            int c16 = u & 15;             // 16B unit within half-row
            const size_t src = (size_t)(i0 + row) * DD + kofE + c16 * 8;
            CP16(sb + OFF_G + row * SKB + kofB + c16 * 16, &d_Gb[src]);
        }
        // coeffs: 32 rows x 16 units per half per array -> 1 per thread
        {
            int row = tid >> 4;           // 0..31
            int c16 = tid & 15;
            const size_t src = (size_t)(q0 + row) * DD + kofE + c16 * 8;
            uint32_t dst = row * SKB + kofB + c16 * 16;
            CP16(sb + OFF_C  + dst, &d_Cb [src]);
            CP16(sb + OFF_A2 + dst, &d_A2b[src]);
            CP16(sb + OFF_AB + dst, &d_ABb[src]);
        }
        CPCOMMIT();
    }

    float s1[2][4], s2[2][4];
    #pragma unroll
    for (int ma = 0; ma < 2; ma++)
        #pragma unroll
        for (int r = 0; r < 4; r++) { s1[ma][r] = 0.f; s2[ma][r] = 0.f; }

    const int subA = lane >> 3;
    const int arow = (lane & 7) + (subA & 1) * 8;
    const int akof = (subA >> 1) * 16;
    const int brow = lane & 7;
    const int bkof = (lane >> 3) * 16;

    const uint32_t gA0 = sb + OFF_G  + (wm * 32 + arow) * SKB + akof;
    const uint32_t gA1 = gA0 + 16 * SKB;
    const uint32_t cB  = sb + OFF_C  + (wn * 8 + brow) * SKB + bkof;
    const uint32_t a2B = sb + OFF_A2 + (wn * 8 + brow) * SKB + bkof;
    const uint32_t abB = sb + OFF_AB + (wn * 8 + brow) * SKB + bkof;

    // ---- mainloop in two halves, pipelined against the loads ----
    #pragma unroll
    for (int h = 0; h < 2; h++) {
        if (h == 0) { CPWAIT1(); } else { CPWAIT0(); }
        __syncthreads();

        #pragma unroll
        for (int pp = 0; pp < 4; pp++) {           // 4 pairs of k16 per half
            const uint32_t pb = (h * 4 + pp) * 64;

            uint32_t bC[4], bA2[4], bAB[4];
            LDSM_X4(bC[0],  bC[1],  bC[2],  bC[3],  cB  + pb);
            LDSM_X4(bA2[0], bA2[1], bA2[2], bA2[3], a2B + pb);
            LDSM_X4(bAB[0], bAB[1], bAB[2], bAB[3], abB + pb);

            #pragma unroll
            for (int e = 0; e < 2; e++) {
                const uint32_t kb = pb + e * 32;
                uint32_t aG[2][4], aG2[2][4];
                LDSM_X4(aG[0][0], aG[0][1], aG[0][2], aG[0][3], gA0 + kb);
                LDSM_X4(aG[1][0], aG[1][1], aG[1][2], aG[1][3], gA1 + kb);
                #pragma unroll
                for (int ma = 0; ma < 2; ma++)
                    #pragma unroll
                    for (int r = 0; r < 4; r++)
                        SQR_BF16X2(aG2[ma][r], aG[ma][r]);

                #pragma unroll
                for (int ma = 0; ma < 2; ma++) {
                    MMA16816(s1[ma], aG[ma],  bC[2*e],  bC[2*e+1]);
                    MMA16816(s2[ma], aG2[ma], bA2[2*e], bA2[2*e+1]);
                    MMA16816(s2[ma], aG[ma],  bAB[2*e], bAB[2*e+1]);
                }
            }
        }
    }

    // ---- epilogue: sigmoid -> smem staging -> coalesced STG.128 ----
    __syncthreads();   // all warps done reading tiles; G region reusable

    float* sOut = (float*)dyn_smem;   // [32 q][pitch 132] fp32 = 16.9 KB
    const float b0 = d_b0;
    const int rbase = lane >> 2;
    const int cbase = 2 * (lane & 3);
    const float c0a = d_c0[q0 + wn * 8 + cbase];
    const float c0b = d_c0[q0 + wn * 8 + cbase + 1];
    #pragma unroll
    for (int ma = 0; ma < 2; ma++) {
        #pragma unroll
        for (int r = 0; r < 4; r++) {
            int il = wm * 32 + ma * 16 + rbase + (r >> 1) * 8;
            int ql = wn * 8 + cbase + (r & 1);
            float v1 = s1[ma][r] + ((r & 1) ? c0b : c0a);
            float v2 = s2[ma][r] + b0;
            float val = v1 * rsqrtf(fmaxf(v2, 1e-24f));
            sOut[ql * OPITCH + il] = 1.f / (1.f + __expf(-val));
        }
    }
    __syncthreads();

    // warp handles q rows 2*warp, 2*warp+1: lane stores float4 (full row coalesced)
    #pragma unroll
    for (int r = 0; r < 2; r++) {
        int ql = warp * 2 + r;
        float4 v = *(const float4*)&sOut[ql * OPITCH + lane * 4];
        *(float4*)&out[(size_t)(q0 + ql) * II + i0 + lane * 4] = v;
    }
}

extern "C" void kernel_launch(void* const* d_in, const int* in_sizes, int n_in,
                              void* d_out, int out_size) {
    const float* query_feats       = (const float*)d_in[0];
    const float* query_img_feats   = (const float*)d_in[1];
    const float* gallery_img_feats = (const float*)d_in[2];
    const float* bn_gamma          = (const float*)d_in[3];
    const float* bn_beta           = (const float*)d_in[4];
    const float* bn_mean           = (const float*)d_in[5];
    const float* bn_var            = (const float*)d_in[6];
    float* out = (float*)d_out;

    cudaFuncSetAttribute(score_kernel,
                         cudaFuncAttributeMaxDynamicSharedMemorySize, SMEM_SZ);

    prep_kernel<<<288, 256>>>(query_feats, query_img_feats, gallery_img_feats,
                              bn_gamma, bn_beta, bn_mean, bn_var);
    dim3 grid(II / TM, QD / TN);
    score_kernel<<<grid, 512, SMEM_SZ>>>(out);
}